// round 4
// baseline (speedup 1.0000x reference)
#include <cuda_runtime.h>
#include <math_constants.h>

// Morphological opening (10x10 min then 10x10 max, SAME pad lo=4/hi=5),
// NHWC [16,512,512,8] f32. Vertical-first fused kernel, van Herk windows.
// Block = 32x32 spatial tile x 2 channels (float2). grid.z = batch*4.
// Stages: V-min (gmem->smem B, fused load), H-min (B->E, +mask), H-max (E->F),
// V-max (F->gmem). Smem 29.8KB -> 5 blocks/SM, 40 warps.

#define B_   16
#define H_   512
#define W_   512
#define TH   32
#define TW   32
#define NT   256

#define NB_C 50            // input columns covered (halo 18)
#define NE   41            // eroded rows/cols with dilation halo
#define FS   33            // F row stride (32 cols + pad)

#define B_OFF 0            // B[c][e]: c in [0,50), e in [0,41), stride 41
#define E_OFF (NB_C * NE)  // 2050; E[c'][e]: 41x41, stride 41
#define F_OFF 0            // F[e][c'']: 41 x 33, overlays B (1353 <= 2050)
#define SMEM_FLOAT2 (E_OFF + NE * NE)          // 3731
#define SMEM_BYTES  (SMEM_FLOAT2 * 8)          // 29848

__device__ __forceinline__ float2 min2(float2 a, float2 b) {
    return make_float2(fminf(a.x,b.x), fminf(a.y,b.y));
}
__device__ __forceinline__ float2 max2(float2 a, float2 b) {
    return make_float2(fmaxf(a.x,b.x), fmaxf(a.y,b.y));
}

__global__ __launch_bounds__(NT, 5)
void opening_kernel(const float2* __restrict__ in2, float2* __restrict__ out2) {
    extern __shared__ float2 sm[];
    float2* Bb = sm + B_OFF;
    float2* E  = sm + E_OFF;
    float2* F  = sm + F_OFF;

    const int b   = blockIdx.z >> 2;
    const int g   = blockIdx.z & 3;
    const int gh0 = blockIdx.y * TH;
    const int gw0 = blockIdx.x * TW;
    const int tid = threadIdx.x;

    const size_t chanBase = (size_t)b * H_ * W_ * 4 + g;
    const float2 INF2  = make_float2( CUDART_INF_F,  CUDART_INF_F);
    const float2 NINF2 = make_float2(-CUDART_INF_F, -CUDART_INF_F);

    // ---- Stage V1: vertical min, fused with gmem load. 250 tasks. ----
    // B[c][e] = min over input rows gr = gh0-8+e .. +9, e in [0,41).
    if (tid < 250) {
        int c   = tid % 50, seg = tid / 50;
        int e0  = seg * 9;
        int n   = (seg == 4) ? 5 : 9;
        int gc  = gw0 + c - 8;
        bool colOK = (gc >= 0 && gc < W_);
        const float2* src = in2 + chanBase + (size_t)gc * 4;
        int grBase = gh0 - 8 + e0;

        float2 x[10];
        #pragma unroll
        for (int t = 0; t < 10; t++) {
            int gr = grBase + t;
            x[t] = (colOK && gr >= 0 && gr < H_) ? src[(size_t)gr * W_ * 4] : INF2;
        }
        #pragma unroll
        for (int j = 8; j >= 0; j--) x[j] = min2(x[j], x[j+1]);
        float2 pr = x[9];
        float2* q = Bb + c * NE + e0;
        q[0] = x[0];
        #pragma unroll
        for (int j = 1; j < 10; j++) {
            if (j >= n) break;
            int gr = grBase + 9 + j;
            float2 xn = (colOK && gr >= 0 && gr < H_) ? src[(size_t)gr * W_ * 4] : INF2;
            pr = min2(pr, xn);
            q[j] = min2(x[j], pr);
        }
    }
    __syncthreads();

    // ---- Stage H1: horizontal min over B -> eroded E, mask -inf off-image. ----
    if (tid < 205) {
        int e   = tid % 41, seg = tid / 41;
        int c0  = seg * 9;
        int n   = (seg == 4) ? 5 : 9;
        const float2* p = Bb + c0 * NE + e;   // step NE per column
        float2 x[10];
        #pragma unroll
        for (int t = 0; t < 10; t++) x[t] = p[t * NE];
        #pragma unroll
        for (int j = 8; j >= 0; j--) x[j] = min2(x[j], x[j+1]);
        float2 pr = x[9];
        int ger = gh0 + e - 4;
        bool rowOK = (ger >= 0 && ger < H_);
        float2* q = E + c0 * NE + e;
        {
            int gec = gw0 + c0 - 4;
            q[0] = (rowOK && gec >= 0 && gec < W_) ? x[0] : NINF2;
        }
        #pragma unroll
        for (int j = 1; j < 10; j++) {
            if (j >= n) break;
            pr = min2(pr, p[(9 + j) * NE]);
            float2 v = min2(x[j], pr);
            int gec = gw0 + c0 + j - 4;
            if (!rowOK || gec < 0 || gec >= W_) v = NINF2;
            q[j * NE] = v;
        }
    }
    __syncthreads();

    // ---- Stage H2: horizontal max over E -> F[e][c''], c'' in [0,32). ----
    if (tid < 164) {
        int e   = tid % 41, seg = tid / 41;
        int c0  = seg * 9;
        int n   = (seg == 3) ? 5 : 9;
        const float2* p = E + c0 * NE + e;
        float2 x[10];
        #pragma unroll
        for (int t = 0; t < 10; t++) x[t] = p[t * NE];
        #pragma unroll
        for (int j = 8; j >= 0; j--) x[j] = max2(x[j], x[j+1]);
        float2 pr = x[9];
        float2* q = F + e * FS + c0;
        q[0] = x[0];
        #pragma unroll
        for (int j = 1; j < 10; j++) {
            if (j >= n) break;
            pr = max2(pr, p[(9 + j) * NE]);
            q[j] = max2(x[j], pr);
        }
    }
    __syncthreads();

    // ---- Stage V2: vertical max over F -> gmem (coalesced). ----
    if (tid < 128) {
        int c   = tid % 32, seg = tid / 32;
        int r0  = seg * 9;
        int n   = (seg == 3) ? 5 : 9;
        const float2* p = F + r0 * FS + c;
        float2 x[10];
        #pragma unroll
        for (int t = 0; t < 10; t++) x[t] = p[t * FS];
        #pragma unroll
        for (int j = 8; j >= 0; j--) x[j] = max2(x[j], x[j+1]);
        float2 pr = x[9];
        float2* q = out2 + chanBase + ((size_t)(gh0 + r0) * W_ + gw0 + c) * 4;
        q[0] = x[0];
        #pragma unroll
        for (int j = 1; j < 10; j++) {
            if (j >= n) break;
            pr = max2(pr, p[(9 + j) * FS]);
            q[(size_t)j * W_ * 4] = max2(x[j], pr);
        }
    }
}

extern "C" void kernel_launch(void* const* d_in, const int* in_sizes, int n_in,
                              void* d_out, int out_size) {
    const float2* in  = (const float2*)d_in[0];
    float2* out = (float2*)d_out;

    cudaFuncSetAttribute(opening_kernel,
                         cudaFuncAttributeMaxDynamicSharedMemorySize, SMEM_BYTES);

    dim3 grid(W_ / TW, H_ / TH, B_ * 4);
    opening_kernel<<<grid, NT, SMEM_BYTES>>>(in, out);
}

// round 5
// speedup vs baseline: 1.2327x; 1.2327x over previous
#include <cuda_runtime.h>
#include <math_constants.h>

// Morphological opening (10x10 min then 10x10 max, SAME pad lo=4/hi=5),
// NHWC [16,512,512,8] f32. Fused, vertical-first, van Herk windows.
// Block = 32(h) x 64(w) tile x ALL 8 channels (2 float4 halves) so every
// gmem access is fully coalesced. Stages:
//   V1: gmem -> B   vertical min fused with load (coalesced LDG.128)
//   H1: B -> E      horizontal min + off-image mask (-inf)
//   H2: E -> F      horizontal max (F overlays B)
//   V2: F -> gmem   vertical max (coalesced STG.128)
// Smem 203KB -> 1 block/SM, 512 threads.

#define H_   512
#define W_   512
#define TH   32
#define TW   64
#define NT   512

#define NE    41            // eroded row index range (TH + 9)
#define NCB   82            // input cols covered (TW + 18)
#define NCE   73            // eroded cols with dilation halo (TW + 9)

#define B_STRIDE_H (NCB * NE)   // 3362
#define E_STRIDE_H (NCE * NE)   // 2993
#define B_OFF 0
#define E_OFF (2 * B_STRIDE_H)  // 6724
#define F_OFF 0                 // 128 x 41 = 5248 <= 6724, overlays B
#define SMEM_F4   (E_OFF + 2 * E_STRIDE_H)   // 12710
#define SMEM_BYTES (SMEM_F4 * 16)            // 203,360

__device__ __forceinline__ float4 min4(float4 a, float4 b) {
    return make_float4(fminf(a.x,b.x), fminf(a.y,b.y), fminf(a.z,b.z), fminf(a.w,b.w));
}
__device__ __forceinline__ float4 max4(float4 a, float4 b) {
    return make_float4(fmaxf(a.x,b.x), fmaxf(a.y,b.y), fmaxf(a.z,b.z), fmaxf(a.w,b.w));
}

__global__ __launch_bounds__(NT, 1)
void opening_kernel(const float4* __restrict__ in4, float4* __restrict__ out4) {
    extern __shared__ float4 sm[];
    float4* Bs = sm + B_OFF;
    float4* Es = sm + E_OFF;
    float4* Fs = sm + F_OFF;

    const int b   = blockIdx.z;
    const int gh0 = blockIdx.y * TH;
    const int gw0 = blockIdx.x * TW;
    const int tid = threadIdx.x;

    const size_t chanBase = (size_t)b * H_ * W_ * 2;   // f4 units
    const float4 INF4  = make_float4( CUDART_INF_F,  CUDART_INF_F,  CUDART_INF_F,  CUDART_INF_F);
    const float4 NINF4 = make_float4(-CUDART_INF_F, -CUDART_INF_F, -CUDART_INF_F, -CUDART_INF_F);

    // ---- V1: vertical min fused with coalesced gmem load. ----
    // B[h][cb][e] = min over input rows gh0+e-8 .. gh0+e+1 at col gw0+cb-8.
    // Tasks: 164 fused cols (cb*2+h) x 5 e-segments = 820.
    #pragma unroll 1
    for (int i = tid; i < 164 * 5; i += NT) {
        int cF  = i % 164, seg = i / 164;
        int e0  = seg * 9;
        int n   = (seg == 4) ? 5 : 9;
        int cb  = cF >> 1, h = cF & 1;
        int gc  = gw0 + cb - 8;
        bool colOK = ((unsigned)gc < W_);
        const float4* src = in4 + chanBase + (size_t)gc * 2 + h;  // row stride W_*2
        int grBase = gh0 - 8 + e0;

        float4 x[10];
        #pragma unroll
        for (int t = 0; t < 10; t++) {
            int gr = grBase + t;
            x[t] = (colOK && (unsigned)gr < H_) ? src[(size_t)gr * (W_ * 2)] : INF4;
        }
        #pragma unroll
        for (int j = 8; j >= 0; j--) x[j] = min4(x[j], x[j+1]);
        float4 pr = x[9];
        float4* q = Bs + h * B_STRIDE_H + cb * NE + e0;
        q[0] = x[0];
        #pragma unroll
        for (int j = 1; j < 9; j++) {
            if (j >= n) break;
            int gr = grBase + 9 + j;
            float4 xn = (colOK && (unsigned)gr < H_) ? src[(size_t)gr * (W_ * 2)] : INF4;
            pr = min4(pr, xn);
            q[j] = min4(x[j], pr);
        }
    }
    __syncthreads();

    // ---- H1: horizontal min over B -> eroded E, mask -inf off-image. ----
    // E[h][c'][e], c' in [0,73). Tasks: 41 e x 2 h x 9 segs = 738.
    #pragma unroll 1
    for (int i = tid; i < 41 * 2 * 9; i += NT) {
        int e   = i % 41;
        int t2  = i / 41;
        int h   = t2 & 1;
        int seg = t2 >> 1;
        int c0  = seg * 9;
        int n   = (seg == 8) ? 1 : 9;
        const float4* p = Bs + h * B_STRIDE_H + c0 * NE + e;   // step NE per col
        float4 x[10];
        #pragma unroll
        for (int t = 0; t < 10; t++) x[t] = p[t * NE];
        #pragma unroll
        for (int j = 8; j >= 0; j--) x[j] = min4(x[j], x[j+1]);
        float4 pr = x[9];
        bool rowOK = ((unsigned)(gh0 + e - 4) < H_);
        float4* q = Es + h * E_STRIDE_H + c0 * NE + e;
        q[0] = (rowOK && (unsigned)(gw0 + c0 - 4) < W_) ? x[0] : NINF4;
        #pragma unroll
        for (int j = 1; j < 9; j++) {
            if (j >= n) break;
            pr = min4(pr, p[(9 + j) * NE]);
            float4 v = min4(x[j], pr);
            if (!rowOK || (unsigned)(gw0 + c0 + j - 4) >= W_) v = NINF4;
            q[j * NE] = v;
        }
    }
    __syncthreads();

    // ---- H2: horizontal max over E -> F[cF''][e]. ----
    // F[(c''*2+h)*41 + e], c'' in [0,64). Tasks: 41 e x 2 h x 8 segs = 656.
    #pragma unroll 1
    for (int i = tid; i < 41 * 2 * 8; i += NT) {
        int e   = i % 41;
        int t2  = i / 41;
        int h   = t2 & 1;
        int seg = t2 >> 1;
        int c0  = seg * 9;
        int n   = (seg == 7) ? 1 : 9;
        const float4* p = Es + h * E_STRIDE_H + c0 * NE + e;
        float4 x[10];
        #pragma unroll
        for (int t = 0; t < 10; t++) x[t] = p[t * NE];
        #pragma unroll
        for (int j = 8; j >= 0; j--) x[j] = max4(x[j], x[j+1]);
        float4 pr = x[9];
        float4* q = Fs + (c0 * 2 + h) * NE + e;
        q[0] = x[0];
        #pragma unroll
        for (int j = 1; j < 9; j++) {
            if (j >= n) break;
            pr = max4(pr, p[(9 + j) * NE]);
            q[j * (2 * NE)] = max4(x[j], pr);
        }
    }
    __syncthreads();

    // ---- V2: vertical max over F -> gmem (coalesced). ----
    // Tasks: 128 fused out cols x 4 r-segments of 8 = 512.
    {
        int i   = tid;
        int cF  = i % 128, seg = i / 128;
        int r0  = seg * 8;
        const float4* p = Fs + cF * NE + r0;   // e = r0 .. r0+16, stride 1
        float4 x[10];
        #pragma unroll
        for (int t = 0; t < 10; t++) x[t] = p[t];
        #pragma unroll
        for (int j = 8; j >= 0; j--) x[j] = max4(x[j], x[j+1]);
        float4 pr = x[9];
        float4* q = out4 + chanBase + ((size_t)(gh0 + r0) * W_ + gw0) * 2 + cF;
        q[0] = x[0];
        #pragma unroll
        for (int j = 1; j < 8; j++) {
            pr = max4(pr, p[9 + j]);
            q[(size_t)j * (W_ * 2)] = max4(x[j], pr);
        }
    }
}

extern "C" void kernel_launch(void* const* d_in, const int* in_sizes, int n_in,
                              void* d_out, int out_size) {
    const float4* in  = (const float4*)d_in[0];
    float4* out = (float4*)d_out;

    cudaFuncSetAttribute(opening_kernel,
                         cudaFuncAttributeMaxDynamicSharedMemorySize, SMEM_BYTES);

    dim3 grid(W_ / TW, H_ / TH, 16);
    opening_kernel<<<grid, NT, SMEM_BYTES>>>(in, out);
}